// round 12
// baseline (speedup 1.0000x reference)
#include <cuda_runtime.h>
#include <cuda_bf16.h>
#include <cuda_fp16.h>
#include <stdint.h>

// Problem constants
#define NN 10000          // nodes
#define EE 160000         // edges
#define DD 512            // feature dim (in == out)
#define DV8 (DD/8)        // 64 uint4-of-half per row
#define CAP 64            // per-node edge bucket capacity (P(deg>=64) ~ 1e-20)

// ---------------- device scratch (no allocs allowed) ----------------
__device__ float g_deg[NN];                       // weighted in-degree sums
__device__ int   g_cnt[NN];                       // per-node bucket fill count
__device__ float g_dinv[NN];                      // rsqrt(1 + deg)
__device__ int   g_esrc[(size_t)NN * CAP];        // bucket: source node
__device__ float g_ew[(size_t)NN * CAP];          // bucket: edge weight
__device__ __half g_h[(size_t)NN * DD];           // h = x @ W (fp16, 10.2 MB)
__device__ __half g_x16[(size_t)NN * DD];         // x in fp16 (10.2 MB)
__device__ __half g_wt[(size_t)DD * DD];          // W^T: [n][k] fp16

// =================== helpers ===================
__device__ __forceinline__ uint32_t smem_to_u32(const void* p) {
    uint32_t a;
    asm("{ .reg .u64 t; cvta.to.shared.u64 t, %1; cvt.u32.u64 %0, t; }"
        : "=r"(a) : "l"(p));
    return a;
}
// XOR swizzle for 128B rows
#define SWZ128(o) ((o) ^ (((o) >> 3) & 0x70))

__device__ __forceinline__ void ldsm_x4(uint32_t r[4], uint32_t addr) {
    asm volatile("ldmatrix.sync.aligned.m8n8.x4.shared.b16 {%0,%1,%2,%3}, [%4];"
                 : "=r"(r[0]), "=r"(r[1]), "=r"(r[2]), "=r"(r[3]) : "r"(addr));
}
__device__ __forceinline__ void mma16816(float c[4], const uint32_t a[4],
                                         uint32_t b0, uint32_t b1) {
    asm volatile(
        "mma.sync.aligned.m16n8k16.row.col.f32.f16.f16.f32 "
        "{%0,%1,%2,%3}, {%4,%5,%6,%7}, {%8,%9}, {%0,%1,%2,%3};"
        : "+f"(c[0]), "+f"(c[1]), "+f"(c[2]), "+f"(c[3])
        : "r"(a[0]), "r"(a[1]), "r"(a[2]), "r"(a[3]), "r"(b0), "r"(b1));
}
__device__ __forceinline__ void cp16(uint32_t dst, const void* src) {
    asm volatile("cp.async.cg.shared.global [%0], [%1], 16;"
                 :: "r"(dst), "l"(src));
}
#define CP_COMMIT() asm volatile("cp.async.commit_group;" ::: "memory")
#define CP_WAIT1()  asm volatile("cp.async.wait_group 1;" ::: "memory")
#define CP_WAIT0()  asm volatile("cp.async.wait_group 0;" ::: "memory")

// =================== prep: x -> fp16; W -> transposed fp16 ===================
// blocks [0,2500): x convert; [2500,3012): W cols
__global__ void prep_kernel(const float* __restrict__ x,
                            const float* __restrict__ W) {
    const int bid = blockIdx.x;
    if (bid < 2500) {
        size_t i = (size_t)bid * 512 + threadIdx.x * 2;   // float4 index (2/thread)
        const float4* xp = (const float4*)x;
#pragma unroll
        for (int q = 0; q < 2; ++q) {
            float4 v = xp[i + q];
            __half2 p0 = __floats2half2_rn(v.x, v.y);
            __half2 p1 = __floats2half2_rn(v.z, v.w);
            uint2 pk;
            pk.x = *(uint32_t*)&p0; pk.y = *(uint32_t*)&p1;
            ((uint2*)g_x16)[i + q] = pk;
        }
    } else {
        int n = bid - 2500;
        for (int k = threadIdx.x; k < DD; k += 256) {
            float v = W[(size_t)k * DD + n];
            g_wt[(size_t)n * DD + k] = __float2half_rn(v);
        }
    }
}

// =================== bucket build (stream 2) ===================
__global__ void degfill_kernel(const int* __restrict__ eidx,
                               const float* __restrict__ ew) {
    int e = blockIdx.x * blockDim.x + threadIdx.x;
    if (e < EE) {
        int r = eidx[e];
        int c = eidx[EE + e];
        float w = ew[e];
        atomicAdd(&g_deg[c], w);
        int p = atomicAdd(&g_cnt[c], 1);
        if (p < CAP) {
            g_esrc[(size_t)c * CAP + p] = r;
            g_ew[(size_t)c * CAP + p]   = w;
        }
    }
}

__global__ void dinv_kernel() {
    int i = blockIdx.x * blockDim.x + threadIdx.x;
    if (i < NN) g_dinv[i] = rsqrtf(1.0f + g_deg[i]);   // self-loop weight 1.0
}

// =================== mma.sync fp16 GEMM: g_h = x16 @ W16 ===================
// CTA tile 128(M) x 128(N), 512 threads (4x4 warps, warp tile 32x32).
// K-chunk 64, 2-stage cp.async. Stage (32KB): A 0..16K | B 16K..32K; SW128.
#define KC 64
#define NCH (DD / KC)            // 8
#define STAGE 32768
#define GEMM_SMEM (2 * STAGE)    // 65536

__device__ __forceinline__ void gemm_load_stage(uint32_t sb, int stOff, int kc,
                                                int tid, int mBase, int nBase) {
    const int kOff = kc * KC;
#pragma unroll
    for (int it = 0; it < 4; ++it) {
        int vv = tid + it * 512;            // 0..2047
        int row = (vv & 1023) >> 3;         // 0..127
        int g   = vv & 7;                   // 16B unit
        const __half* srcp;
        int region;
        size_t srcRow;
        if (vv < 1024) {
            int m = mBase + row; if (m > NN - 1) m = NN - 1;
            srcp = g_x16;
            region = 0;
            srcRow = (size_t)m;
        } else {
            srcp = g_wt;
            region = 16384;
            srcRow = (size_t)(nBase + row);
        }
        cp16(sb + stOff + region + SWZ128(row * 128 + g * 16),
             srcp + srcRow * DD + kOff + g * 8);
    }
}

__global__ void __launch_bounds__(512, 2)
gemm_kernel() {
    extern __shared__ char smem[];
    const uint32_t sb = smem_to_u32(smem);
    const int tid  = threadIdx.x;
    const int wid  = tid >> 5;
    const int lane = tid & 31;
    const int wy   = wid >> 2;            // 0..3  (M)
    const int wx   = wid & 3;             // 0..3  (N)
    const int mBase = blockIdx.y * 128;
    const int nBase = blockIdx.x * 128;

    float c[2][4][4];                      // warp tile 32x32
#pragma unroll
    for (int i = 0; i < 2; ++i)
#pragma unroll
        for (int j = 0; j < 4; ++j)
#pragma unroll
            for (int r = 0; r < 4; ++r) c[i][j][r] = 0.0f;

    const int aRow = wy * 32 + (lane & 15);
    const int aKu  = (lane >> 4);
    const int bRow = wx * 32 + (lane & 7) + ((lane >> 4) & 1) * 8;
    const int bKu  = ((lane >> 3) & 1);

    gemm_load_stage(sb, 0, 0, tid, mBase, nBase);
    CP_COMMIT();

    for (int kc = 0; kc < NCH; ++kc) {
        const int stOff = (kc & 1) * STAGE;
        if (kc + 1 < NCH) {
            gemm_load_stage(sb, ((kc + 1) & 1) * STAGE, kc + 1, tid, mBase, nBase);
            CP_COMMIT();
            CP_WAIT1();
        } else {
            CP_WAIT0();
        }
        __syncthreads();

#pragma unroll
        for (int k16 = 0; k16 < 4; ++k16) {
            const int kb = k16 * 2;
            uint32_t a[2][4], b[2][4];
#pragma unroll
            for (int mt = 0; mt < 2; ++mt) {
                int off = SWZ128((aRow + mt * 16) * 128 + (kb + aKu) * 16);
                ldsm_x4(a[mt], sb + stOff + 0 + off);
            }
#pragma unroll
            for (int pr = 0; pr < 2; ++pr) {
                int off = SWZ128((bRow + pr * 16) * 128 + (kb + bKu) * 16);
                ldsm_x4(b[pr], sb + stOff + 16384 + off);
            }
#pragma unroll
            for (int mt = 0; mt < 2; ++mt)
#pragma unroll
                for (int nt = 0; nt < 4; ++nt)
                    mma16816(c[mt][nt], a[mt], b[nt >> 1][(nt & 1) * 2],
                             b[nt >> 1][(nt & 1) * 2 + 1]);
        }
        __syncthreads();
    }

    // epilogue: half2 stores to g_h
    const int erow = mBase + wy * 32 + (lane >> 2);
    const int ecol = nBase + wx * 32 + (lane & 3) * 2;
#pragma unroll
    for (int mt = 0; mt < 2; ++mt) {
#pragma unroll
        for (int nt = 0; nt < 4; ++nt) {
            int r0 = erow + mt * 16;
            int cc = ecol + nt * 8;
            if (r0 < NN) {
                __half2 p = __floats2half2_rn(c[mt][nt][0], c[mt][nt][1]);
                *(__half2*)&g_h[(size_t)r0 * DD + cc] = p;
            }
            if (r0 + 8 < NN) {
                __half2 p = __floats2half2_rn(c[mt][nt][2], c[mt][nt][3]);
                *(__half2*)&g_h[(size_t)(r0 + 8) * DD + cc] = p;
            }
        }
    }
}

// =================== aggregation (fp16 rows, 64 threads/node, unroll 4) ===================
__device__ __forceinline__ void fma_h8(float acc[8], uint4 v, float n) {
    __half2* hp = (__half2*)&v;
#pragma unroll
    for (int q = 0; q < 4; ++q) {
        float2 f = __half22float2(hp[q]);
        acc[q * 2 + 0] += f.x * n;
        acc[q * 2 + 1] += f.y * n;
    }
}

__global__ __launch_bounds__(64)
void agg_kernel(const float* __restrict__ bias,
                float* __restrict__ out) {
    const int i = blockIdx.x;
    const int t = threadIdx.x;          // 0..63, owns 8 columns
    const uint4* hb = (const uint4*)g_h;

    const float di = g_dinv[i];
    float acc[8];
    {
        const float4* bp = (const float4*)(bias + t * 8);
        float4 b0 = bp[0], b1 = bp[1];
        acc[0] = b0.x; acc[1] = b0.y; acc[2] = b0.z; acc[3] = b0.w;
        acc[4] = b1.x; acc[5] = b1.y; acc[6] = b1.z; acc[7] = b1.w;
    }
    // self loop: norm = di * 1.0 * di
    fma_h8(acc, hb[(size_t)i * DV8 + t], di * di);

    const int cnt0 = g_cnt[i];
    const int cnt = (cnt0 < CAP) ? cnt0 : CAP;
    const int base = i * CAP;
    int k = 0;
    for (; k + 3 < cnt; k += 4) {
        int r0 = g_esrc[base + k],     r1 = g_esrc[base + k + 1];
        int r2 = g_esrc[base + k + 2], r3 = g_esrc[base + k + 3];
        float n0 = g_dinv[r0] * g_ew[base + k]     * di;
        float n1 = g_dinv[r1] * g_ew[base + k + 1] * di;
        float n2 = g_dinv[r2] * g_ew[base + k + 2] * di;
        float n3 = g_dinv[r3] * g_ew[base + k + 3] * di;
        uint4 v0 = hb[(size_t)r0 * DV8 + t];
        uint4 v1 = hb[(size_t)r1 * DV8 + t];
        uint4 v2 = hb[(size_t)r2 * DV8 + t];
        uint4 v3 = hb[(size_t)r3 * DV8 + t];
        fma_h8(acc, v0, n0);
        fma_h8(acc, v1, n1);
        fma_h8(acc, v2, n2);
        fma_h8(acc, v3, n3);
    }
    for (; k < cnt; ++k) {
        int r0 = g_esrc[base + k];
        float n0 = g_dinv[r0] * g_ew[base + k] * di;
        fma_h8(acc, hb[(size_t)r0 * DV8 + t], n0);
    }

    float4* op = (float4*)(out + (size_t)i * DD + t * 8);
    op[0] = make_float4(acc[0], acc[1], acc[2], acc[3]);
    op[1] = make_float4(acc[4], acc[5], acc[6], acc[7]);
}

// =================== launcher ===================
extern "C" void kernel_launch(void* const* d_in, const int* in_sizes, int n_in,
                              void* d_out, int out_size) {
    const float* x    = (const float*)d_in[0];       // [NN, DD]
    const int*   eidx = (const int*)d_in[1];         // [2, EE] int32
    const float* ea   = (const float*)d_in[2];       // [EE]
    const float* W    = (const float*)d_in[3];       // [DD, DD]
    const float* b    = (const float*)d_in[4];       // [DD]
    float*       out  = (float*)d_out;               // [NN, DD]

    static cudaStream_t s2 = nullptr;
    static cudaEvent_t evFork = nullptr, evJoin = nullptr;
    static void *p_deg = nullptr, *p_cnt = nullptr;
    if (s2 == nullptr) {
        cudaStreamCreateWithFlags(&s2, cudaStreamNonBlocking);
        cudaEventCreateWithFlags(&evFork, cudaEventDisableTiming);
        cudaEventCreateWithFlags(&evJoin, cudaEventDisableTiming);
        cudaGetSymbolAddress(&p_deg, g_deg);
        cudaGetSymbolAddress(&p_cnt, g_cnt);
        cudaFuncSetAttribute(gemm_kernel,
                             cudaFuncAttributeMaxDynamicSharedMemorySize, GEMM_SMEM);
    }

    // fork bucket-build chain onto s2
    cudaEventRecord(evFork, 0);
    cudaStreamWaitEvent(s2, evFork, 0);
    cudaMemsetAsync(p_deg, 0, NN * sizeof(float), s2);
    cudaMemsetAsync(p_cnt, 0, NN * sizeof(int), s2);
    degfill_kernel<<<(EE + 255) / 256, 256, 0, s2>>>(eidx, ea);
    dinv_kernel<<<(NN + 255) / 256, 256, 0, s2>>>();
    cudaEventRecord(evJoin, s2);

    // main stream: prep then GEMM
    prep_kernel<<<3012, 256>>>(x, W);
    dim3 ggrid(DD / 128, (NN + 127) / 128);          // (4, 79)
    gemm_kernel<<<ggrid, 512, GEMM_SMEM>>>();

    // join, then aggregate
    cudaStreamWaitEvent(0, evJoin, 0);
    agg_kernel<<<NN, 64>>>(b, out);
}

// round 13
// speedup vs baseline: 1.0202x; 1.0202x over previous
#include <cuda_runtime.h>
#include <cuda_bf16.h>
#include <cuda_fp16.h>
#include <stdint.h>

// Problem constants
#define NN 10000          // nodes
#define EE 160000         // edges
#define DD 512            // feature dim (in == out)
#define DV8 (DD/8)        // 64 uint4-of-half per row
#define CAP 64            // per-node edge bucket capacity (P(deg>=64) ~ 1e-20)

// ---------------- device scratch (no allocs allowed) ----------------
__device__ float g_deg[NN];                       // weighted in-degree sums
__device__ int   g_cnt[NN];                       // per-node bucket fill count
__device__ float g_dinv[NN];                      // rsqrt(1 + deg)
__device__ int   g_esrc[(size_t)NN * CAP];        // bucket: source node
__device__ float g_ew[(size_t)NN * CAP];          // bucket: edge weight
__device__ __half g_h[(size_t)NN * DD];           // h = x @ W (fp16, 10.2 MB)
__device__ __half g_x16[(size_t)NN * DD];         // x in fp16 (10.2 MB)
__device__ __half g_wt[(size_t)DD * DD];          // W^T: [n][k] fp16

// =================== helpers ===================
__device__ __forceinline__ uint32_t smem_to_u32(const void* p) {
    uint32_t a;
    asm("{ .reg .u64 t; cvta.to.shared.u64 t, %1; cvt.u32.u64 %0, t; }"
        : "=r"(a) : "l"(p));
    return a;
}
// XOR swizzle for 64B rows
#define SWZ64(o) ((o) ^ (((o) >> 3) & 0x30))

__device__ __forceinline__ void ldsm_x4(uint32_t r[4], uint32_t addr) {
    asm volatile("ldmatrix.sync.aligned.m8n8.x4.shared.b16 {%0,%1,%2,%3}, [%4];"
                 : "=r"(r[0]), "=r"(r[1]), "=r"(r[2]), "=r"(r[3]) : "r"(addr));
}
__device__ __forceinline__ void mma16816(float c[4], const uint32_t a[4],
                                         uint32_t b0, uint32_t b1) {
    asm volatile(
        "mma.sync.aligned.m16n8k16.row.col.f32.f16.f16.f32 "
        "{%0,%1,%2,%3}, {%4,%5,%6,%7}, {%8,%9}, {%0,%1,%2,%3};"
        : "+f"(c[0]), "+f"(c[1]), "+f"(c[2]), "+f"(c[3])
        : "r"(a[0]), "r"(a[1]), "r"(a[2]), "r"(a[3]), "r"(b0), "r"(b1));
}
__device__ __forceinline__ void cp16(uint32_t dst, const void* src) {
    asm volatile("cp.async.cg.shared.global [%0], [%1], 16;"
                 :: "r"(dst), "l"(src));
}
#define CP_COMMIT() asm volatile("cp.async.commit_group;" ::: "memory")
#define CP_WAIT2()  asm volatile("cp.async.wait_group 2;" ::: "memory")
#define CP_WAIT1()  asm volatile("cp.async.wait_group 1;" ::: "memory")
#define CP_WAIT0()  asm volatile("cp.async.wait_group 0;" ::: "memory")

// =================== prep: x -> fp16; W -> transposed fp16 ===================
// blocks [0,2500): x convert; [2500,3012): W cols
__global__ void prep_kernel(const float* __restrict__ x,
                            const float* __restrict__ W) {
    const int bid = blockIdx.x;
    if (bid < 2500) {
        size_t i = (size_t)bid * 512 + threadIdx.x * 2;   // float4 index (2/thread)
        const float4* xp = (const float4*)x;
#pragma unroll
        for (int q = 0; q < 2; ++q) {
            float4 v = xp[i + q];
            __half2 p0 = __floats2half2_rn(v.x, v.y);
            __half2 p1 = __floats2half2_rn(v.z, v.w);
            uint2 pk;
            pk.x = *(uint32_t*)&p0; pk.y = *(uint32_t*)&p1;
            ((uint2*)g_x16)[i + q] = pk;
        }
    } else {
        int n = bid - 2500;
        for (int k = threadIdx.x; k < DD; k += 256) {
            float v = W[(size_t)k * DD + n];
            g_wt[(size_t)n * DD + k] = __float2half_rn(v);
        }
    }
}

// =================== bucket build (stream 2) ===================
__global__ void degfill_kernel(const int* __restrict__ eidx,
                               const float* __restrict__ ew) {
    int e = blockIdx.x * blockDim.x + threadIdx.x;
    if (e < EE) {
        int r = eidx[e];
        int c = eidx[EE + e];
        float w = ew[e];
        atomicAdd(&g_deg[c], w);
        int p = atomicAdd(&g_cnt[c], 1);
        if (p < CAP) {
            g_esrc[(size_t)c * CAP + p] = r;
            g_ew[(size_t)c * CAP + p]   = w;
        }
    }
}

__global__ void dinv_kernel() {
    int i = blockIdx.x * blockDim.x + threadIdx.x;
    if (i < NN) g_dinv[i] = rsqrtf(1.0f + g_deg[i]);   // self-loop weight 1.0
}

// =================== mma.sync fp16 GEMM: g_h = x16 @ W16 ===================
// CTA tile 128(M) x 128(N), 128 threads (2x2 warps, warp tile 64x64 - CUTLASS shape).
// K-chunk 32, 3-stage cp.async. Stage (16KB): A 0..8K | B 8K..16K ; 64B rows, SW64.
#define KC 32
#define NCH (DD / KC)            // 16
#define STAGE 16384
#define NSTG 3
#define GEMM_SMEM (NSTG * STAGE) // 49152

__device__ __forceinline__ void gemm_load_stage(uint32_t sb, int stOff, int kc,
                                                int tid, int mBase, int nBase) {
    const int kOff = kc * KC;
#pragma unroll
    for (int it = 0; it < 8; ++it) {
        int vv = tid + it * 128;            // 0..1023
        int row = (vv & 511) >> 2;          // 0..127
        int g   = vv & 3;                   // 16B unit
        const __half* srcp;
        int region;
        size_t srcRow;
        if (vv < 512) {
            int m = mBase + row; if (m > NN - 1) m = NN - 1;
            srcp = g_x16;
            region = 0;
            srcRow = (size_t)m;
        } else {
            srcp = g_wt;
            region = 8192;
            srcRow = (size_t)(nBase + row);
        }
        cp16(sb + stOff + region + SWZ64(row * 64 + g * 16),
             srcp + srcRow * DD + kOff + g * 8);
    }
}

__global__ void __launch_bounds__(128, 2)
gemm_kernel() {
    extern __shared__ char smem[];
    const uint32_t sb = smem_to_u32(smem);
    const int tid  = threadIdx.x;
    const int wid  = tid >> 5;
    const int lane = tid & 31;
    const int wy   = wid >> 1;            // 0..1  (M)
    const int wx   = wid & 1;             // 0..1  (N)
    const int mBase = blockIdx.y * 128;
    const int nBase = blockIdx.x * 128;

    float c[4][8][4];                      // warp tile 64x64
#pragma unroll
    for (int i = 0; i < 4; ++i)
#pragma unroll
        for (int j = 0; j < 8; ++j)
#pragma unroll
            for (int r = 0; r < 4; ++r) c[i][j][r] = 0.0f;

    const int aRow = wy * 64 + (lane & 15);
    const int aKu  = (lane >> 4);
    const int bRow = wx * 64 + (lane & 7) + ((lane >> 4) & 1) * 8;
    const int bKu  = ((lane >> 3) & 1);

    gemm_load_stage(sb, 0, 0, tid, mBase, nBase);
    CP_COMMIT();
    gemm_load_stage(sb, STAGE, 1, tid, mBase, nBase);
    CP_COMMIT();

    for (int kc = 0; kc < NCH; ++kc) {
        const int stOff = (kc % NSTG) * STAGE;
        if (kc + 2 < NCH) {
            gemm_load_stage(sb, ((kc + 2) % NSTG) * STAGE, kc + 2, tid, mBase, nBase);
            CP_COMMIT();
            CP_WAIT2();
        } else if (kc + 1 < NCH) {
            CP_WAIT1();
        } else {
            CP_WAIT0();
        }
        __syncthreads();

#pragma unroll
        for (int k16 = 0; k16 < 2; ++k16) {
            const int kb = k16 * 2;
            uint32_t a[4][4], b[4][4];
#pragma unroll
            for (int mt = 0; mt < 4; ++mt) {
                int off = SWZ64((aRow + mt * 16) * 64 + (kb + aKu) * 16);
                ldsm_x4(a[mt], sb + stOff + 0 + off);
            }
#pragma unroll
            for (int pr = 0; pr < 4; ++pr) {
                int off = SWZ64((bRow + pr * 16) * 64 + (kb + bKu) * 16);
                ldsm_x4(b[pr], sb + stOff + 8192 + off);
            }
#pragma unroll
            for (int mt = 0; mt < 4; ++mt)
#pragma unroll
                for (int nt = 0; nt < 8; ++nt)
                    mma16816(c[mt][nt], a[mt], b[nt >> 1][(nt & 1) * 2],
                             b[nt >> 1][(nt & 1) * 2 + 1]);
        }
        __syncthreads();
    }

    // epilogue: half2 stores to g_h
    const int erow = mBase + wy * 64 + (lane >> 2);
    const int ecol = nBase + wx * 64 + (lane & 3) * 2;
#pragma unroll
    for (int mt = 0; mt < 4; ++mt) {
#pragma unroll
        for (int nt = 0; nt < 8; ++nt) {
            int r0 = erow + mt * 16;
            int cc = ecol + nt * 8;
            if (r0 < NN) {
                __half2 p = __floats2half2_rn(c[mt][nt][0], c[mt][nt][1]);
                *(__half2*)&g_h[(size_t)r0 * DD + cc] = p;
            }
            if (r0 + 8 < NN) {
                __half2 p = __floats2half2_rn(c[mt][nt][2], c[mt][nt][3]);
                *(__half2*)&g_h[(size_t)(r0 + 8) * DD + cc] = p;
            }
        }
    }
}

// =================== aggregation (fp16 rows, 64 threads/node, unroll 4) ===================
__device__ __forceinline__ void fma_h8(float acc[8], uint4 v, float n) {
    __half2* hp = (__half2*)&v;
#pragma unroll
    for (int q = 0; q < 4; ++q) {
        float2 f = __half22float2(hp[q]);
        acc[q * 2 + 0] += f.x * n;
        acc[q * 2 + 1] += f.y * n;
    }
}

__global__ __launch_bounds__(64)
void agg_kernel(const float* __restrict__ bias,
                float* __restrict__ out) {
    const int i = blockIdx.x;
    const int t = threadIdx.x;          // 0..63, owns 8 columns
    const uint4* hb = (const uint4*)g_h;

    const float di = g_dinv[i];
    float acc[8];
    {
        const float4* bp = (const float4*)(bias + t * 8);
        float4 b0 = bp[0], b1 = bp[1];
        acc[0] = b0.x; acc[1] = b0.y; acc[2] = b0.z; acc[3] = b0.w;
        acc[4] = b1.x; acc[5] = b1.y; acc[6] = b1.z; acc[7] = b1.w;
    }
    // self loop: norm = di * 1.0 * di
    fma_h8(acc, hb[(size_t)i * DV8 + t], di * di);

    const int cnt0 = g_cnt[i];
    const int cnt = (cnt0 < CAP) ? cnt0 : CAP;
    const int base = i * CAP;
    int k = 0;
    for (; k + 3 < cnt; k += 4) {
        int r0 = g_esrc[base + k],     r1 = g_esrc[base + k + 1];
        int r2 = g_esrc[base + k + 2], r3 = g_esrc[base + k + 3];
        float n0 = g_dinv[r0] * g_ew[base + k]     * di;
        float n1 = g_dinv[r1] * g_ew[base + k + 1] * di;
        float n2 = g_dinv[r2] * g_ew[base + k + 2] * di;
        float n3 = g_dinv[r3] * g_ew[base + k + 3] * di;
        uint4 v0 = hb[(size_t)r0 * DV8 + t];
        uint4 v1 = hb[(size_t)r1 * DV8 + t];
        uint4 v2 = hb[(size_t)r2 * DV8 + t];
        uint4 v3 = hb[(size_t)r3 * DV8 + t];
        fma_h8(acc, v0, n0);
        fma_h8(acc, v1, n1);
        fma_h8(acc, v2, n2);
        fma_h8(acc, v3, n3);
    }
    for (; k < cnt; ++k) {
        int r0 = g_esrc[base + k];
        float n0 = g_dinv[r0] * g_ew[base + k] * di;
        fma_h8(acc, hb[(size_t)r0 * DV8 + t], n0);
    }

    float4* op = (float4*)(out + (size_t)i * DD + t * 8);
    op[0] = make_float4(acc[0], acc[1], acc[2], acc[3]);
    op[1] = make_float4(acc[4], acc[5], acc[6], acc[7]);
}

// =================== launcher ===================
extern "C" void kernel_launch(void* const* d_in, const int* in_sizes, int n_in,
                              void* d_out, int out_size) {
    const float* x    = (const float*)d_in[0];       // [NN, DD]
    const int*   eidx = (const int*)d_in[1];         // [2, EE] int32
    const float* ea   = (const float*)d_in[2];       // [EE]
    const float* W    = (const float*)d_in[3];       // [DD, DD]
    const float* b    = (const float*)d_in[4];       // [DD]
    float*       out  = (float*)d_out;               // [NN, DD]

    static cudaStream_t s2 = nullptr;
    static cudaEvent_t evFork = nullptr, evJoin = nullptr;
    static void *p_deg = nullptr, *p_cnt = nullptr;
    if (s2 == nullptr) {
        cudaStreamCreateWithFlags(&s2, cudaStreamNonBlocking);
        cudaEventCreateWithFlags(&evFork, cudaEventDisableTiming);
        cudaEventCreateWithFlags(&evJoin, cudaEventDisableTiming);
        cudaGetSymbolAddress(&p_deg, g_deg);
        cudaGetSymbolAddress(&p_cnt, g_cnt);
        cudaFuncSetAttribute(gemm_kernel,
                             cudaFuncAttributeMaxDynamicSharedMemorySize, GEMM_SMEM);
    }

    // fork bucket-build chain onto s2
    cudaEventRecord(evFork, 0);
    cudaStreamWaitEvent(s2, evFork, 0);
    cudaMemsetAsync(p_deg, 0, NN * sizeof(float), s2);
    cudaMemsetAsync(p_cnt, 0, NN * sizeof(int), s2);
    degfill_kernel<<<(EE + 255) / 256, 256, 0, s2>>>(eidx, ea);
    dinv_kernel<<<(NN + 255) / 256, 256, 0, s2>>>();
    cudaEventRecord(evJoin, s2);

    // main stream: prep then GEMM
    prep_kernel<<<3012, 256>>>(x, W);
    dim3 ggrid(DD / 128, (NN + 127) / 128);          // (4, 79)
    gemm_kernel<<<ggrid, 128, GEMM_SMEM>>>();

    // join, then aggregate
    cudaStreamWaitEvent(0, evJoin, 0);
    agg_kernel<<<NN, 64>>>(b, out);
}

// round 15
// speedup vs baseline: 1.1047x; 1.0829x over previous
#include <cuda_runtime.h>
#include <cuda_bf16.h>
#include <cuda_fp16.h>
#include <stdint.h>

// Problem constants
#define NN 10000          // nodes
#define EE 160000         // edges
#define DD 512            // feature dim (in == out)
#define DV8 (DD/8)        // 64 uint4-of-half per row
#define CAP 64            // per-node edge bucket capacity (P(deg>=64) ~ 1e-20)

// ---------------- device scratch (no allocs allowed) ----------------
__device__ float g_deg[NN];                       // weighted in-degree sums
__device__ int   g_cnt[NN];                       // per-node bucket fill count
__device__ float g_dinv[NN];                      // rsqrt(1 + deg)
__device__ int   g_esrc[(size_t)NN * CAP];        // bucket: source node
__device__ float g_ew[(size_t)NN * CAP];          // bucket: edge weight
__device__ __half g_h[(size_t)NN * DD];           // h = x @ W (fp16, 10.2 MB)
__device__ __half g_x16[(size_t)NN * DD];         // x in fp16 (10.2 MB)
__device__ __half g_wt[(size_t)DD * DD];          // W^T: [n][k] fp16

// =================== helpers ===================
__device__ __forceinline__ uint32_t smem_to_u32(const void* p) {
    uint32_t a;
    asm("{ .reg .u64 t; cvta.to.shared.u64 t, %1; cvt.u32.u64 %0, t; }"
        : "=r"(a) : "l"(p));
    return a;
}
// XOR swizzle for 64B rows
#define SWZ64(o) ((o) ^ (((o) >> 3) & 0x30))

__device__ __forceinline__ void ldsm_x4(uint32_t r[4], uint32_t addr) {
    asm volatile("ldmatrix.sync.aligned.m8n8.x4.shared.b16 {%0,%1,%2,%3}, [%4];"
                 : "=r"(r[0]), "=r"(r[1]), "=r"(r[2]), "=r"(r[3]) : "r"(addr));
}
__device__ __forceinline__ void mma16816(float c[4], const uint32_t a[4],
                                         uint32_t b0, uint32_t b1) {
    asm volatile(
        "mma.sync.aligned.m16n8k16.row.col.f32.f16.f16.f32 "
        "{%0,%1,%2,%3}, {%4,%5,%6,%7}, {%8,%9}, {%0,%1,%2,%3};"
        : "+f"(c[0]), "+f"(c[1]), "+f"(c[2]), "+f"(c[3])
        : "r"(a[0]), "r"(a[1]), "r"(a[2]), "r"(a[3]), "r"(b0), "r"(b1));
}
__device__ __forceinline__ void cp16(uint32_t dst, const void* src) {
    asm volatile("cp.async.cg.shared.global [%0], [%1], 16;"
                 :: "r"(dst), "l"(src));
}
#define CP_COMMIT() asm volatile("cp.async.commit_group;" ::: "memory")
#define CP_WAIT2()  asm volatile("cp.async.wait_group 2;" ::: "memory")
#define CP_WAIT1()  asm volatile("cp.async.wait_group 1;" ::: "memory")
#define CP_WAIT0()  asm volatile("cp.async.wait_group 0;" ::: "memory")

// =================== prep: x -> fp16; W -> transposed fp16 ===================
// blocks [0,2500): x convert; [2500,3012): W cols
__global__ void prep_kernel(const float* __restrict__ x,
                            const float* __restrict__ W) {
    const int bid = blockIdx.x;
    if (bid < 2500) {
        size_t i = (size_t)bid * 512 + threadIdx.x * 2;   // float4 index (2/thread)
        const float4* xp = (const float4*)x;
#pragma unroll
        for (int q = 0; q < 2; ++q) {
            float4 v = xp[i + q];
            __half2 p0 = __floats2half2_rn(v.x, v.y);
            __half2 p1 = __floats2half2_rn(v.z, v.w);
            uint2 pk;
            pk.x = *(uint32_t*)&p0; pk.y = *(uint32_t*)&p1;
            ((uint2*)g_x16)[i + q] = pk;
        }
    } else {
        int n = bid - 2500;
        for (int k = threadIdx.x; k < DD; k += 256) {
            float v = W[(size_t)k * DD + n];
            g_wt[(size_t)n * DD + k] = __float2half_rn(v);
        }
    }
}

// =================== bucket build (stream 2) ===================
__global__ void degfill_kernel(const int* __restrict__ eidx,
                               const float* __restrict__ ew) {
    int e = blockIdx.x * blockDim.x + threadIdx.x;
    if (e < EE) {
        int r = eidx[e];
        int c = eidx[EE + e];
        float w = ew[e];
        atomicAdd(&g_deg[c], w);
        int p = atomicAdd(&g_cnt[c], 1);
        if (p < CAP) {
            g_esrc[(size_t)c * CAP + p] = r;
            g_ew[(size_t)c * CAP + p]   = w;
        }
    }
}

__global__ void dinv_kernel() {
    int i = blockIdx.x * blockDim.x + threadIdx.x;
    if (i < NN) g_dinv[i] = rsqrtf(1.0f + g_deg[i]);   // self-loop weight 1.0
}

// =================== mma.sync fp16 GEMM: g_h = x16 @ W16 ===================
// CTA tile 160(M) x 128(N), 256 threads (2x4 warps, warp tile 80x32).
// Grid (4, 63) = 252 CTAs <= 296 slots -> SINGLE WAVE at 2 CTAs/SM.
// K-chunk 32, 3-stage cp.async. Stage (18KB): A 0..10240 | B 10240..18432; SW64.
#define MT 160
#define KC 32
#define NCH (DD / KC)            // 16
#define A_BYTES (MT * 64)        // 10240
#define B_BYTES (128 * 64)       // 8192
#define STAGE (A_BYTES + B_BYTES)// 18432
#define NSTG 3
#define GEMM_SMEM (NSTG * STAGE) // 55296
#define NVEC ((A_BYTES + B_BYTES) / 16)  // 1152 16B vectors
#define AVEC (A_BYTES / 16)              // 640

__device__ __forceinline__ void gemm_load_stage(uint32_t sb, int stOff, int kc,
                                                int tid, int mBase, int nBase) {
    const int kOff = kc * KC;
#pragma unroll
    for (int it = 0; it < 5; ++it) {
        int vv = tid + it * 256;            // 0..1279
        if (vv >= NVEC) break;
        int region, row, g;
        const __half* srcp;
        size_t srcRow;
        if (vv < AVEC) {
            row = vv >> 2; g = vv & 3;
            int m = mBase + row; if (m > NN - 1) m = NN - 1;
            srcp = g_x16;
            region = 0;
            srcRow = (size_t)m;
        } else {
            int u = vv - AVEC;
            row = u >> 2; g = u & 3;
            srcp = g_wt;
            region = A_BYTES;
            srcRow = (size_t)(nBase + row);
        }
        cp16(sb + stOff + region + SWZ64(row * 64 + g * 16),
             srcp + srcRow * DD + kOff + g * 8);
    }
}

__global__ void __launch_bounds__(256, 2)
gemm_kernel() {
    extern __shared__ char smem[];
    const uint32_t sb = smem_to_u32(smem);
    const int tid  = threadIdx.x;
    const int wid  = tid >> 5;
    const int lane = tid & 31;
    const int wy   = wid >> 2;            // 0..1  (M)
    const int wx   = wid & 3;             // 0..3  (N)
    const int mBase = blockIdx.y * MT;
    const int nBase = blockIdx.x * 128;

    float c[5][4][4];                      // warp tile 80x32
#pragma unroll
    for (int i = 0; i < 5; ++i)
#pragma unroll
        for (int j = 0; j < 4; ++j)
#pragma unroll
            for (int r = 0; r < 4; ++r) c[i][j][r] = 0.0f;

    const int aRow = wy * 80 + (lane & 15);
    const int aKu  = (lane >> 4);
    const int bRow = wx * 32 + (lane & 7) + ((lane >> 4) & 1) * 8;
    const int bKu  = ((lane >> 3) & 1);

    gemm_load_stage(sb, 0, 0, tid, mBase, nBase);
    CP_COMMIT();
    gemm_load_stage(sb, STAGE, 1, tid, mBase, nBase);
    CP_COMMIT();

    for (int kc = 0; kc < NCH; ++kc) {
        const int stOff = (kc % NSTG) * STAGE;
        if (kc + 2 < NCH) {
            gemm_load_stage(sb, ((kc + 2) % NSTG) * STAGE, kc + 2, tid, mBase, nBase);
            CP_COMMIT();
            CP_WAIT2();
        } else if (kc + 1 < NCH) {
            CP_WAIT1();
        } else {
            CP_WAIT0();
        }
        __syncthreads();

#pragma unroll
        for (int k16 = 0; k16 < 2; ++k16) {
            const int kb = k16 * 2;
            uint32_t a[5][4], b[2][4];
#pragma unroll
            for (int mt = 0; mt < 5; ++mt) {
                int off = SWZ64((aRow + mt * 16) * 64 + (kb + aKu) * 16);
                ldsm_x4(a[mt], sb + stOff + 0 + off);
            }
#pragma unroll
            for (int pr = 0; pr < 2; ++pr) {
                int off = SWZ64((bRow + pr * 16) * 64 + (kb + bKu) * 16);
                ldsm_x4(b[pr], sb + stOff + A_BYTES + off);
            }
#pragma unroll
            for (int mt = 0; mt < 5; ++mt)
#pragma unroll
                for (int nt = 0; nt < 4; ++nt)
                    mma16816(c[mt][nt], a[mt], b[nt >> 1][(nt & 1) * 2],
                             b[nt >> 1][(nt & 1) * 2 + 1]);
        }
        __syncthreads();
    }

    // epilogue: half2 stores to g_h
    const int erow = mBase + wy * 80 + (lane >> 2);
    const int ecol = nBase + wx * 32 + (lane & 3) * 2;
#pragma unroll
    for (int mt = 0; mt < 5; ++mt) {
#pragma unroll
        for (int nt = 0; nt < 4; ++nt) {
            int r0 = erow + mt * 16;
            int cc = ecol + nt * 8;
            if (r0 < NN) {
                __half2 p = __floats2half2_rn(c[mt][nt][0], c[mt][nt][1]);
                *(__half2*)&g_h[(size_t)r0 * DD + cc] = p;
            }
            if (r0 + 8 < NN) {
                __half2 p = __floats2half2_rn(c[mt][nt][2], c[mt][nt][3]);
                *(__half2*)&g_h[(size_t)(r0 + 8) * DD + cc] = p;
            }
        }
    }
}

// =================== aggregation (fp16 rows, 64 threads/node, unroll 4) ===================
__device__ __forceinline__ void fma_h8(float acc[8], uint4 v, float n) {
    __half2* hp = (__half2*)&v;
#pragma unroll
    for (int q = 0; q < 4; ++q) {
        float2 f = __half22float2(hp[q]);
        acc[q * 2 + 0] += f.x * n;
        acc[q * 2 + 1] += f.y * n;
    }
}

__global__ __launch_bounds__(64)
void agg_kernel(const float* __restrict__ bias,
                float* __restrict__ out) {
    const int i = blockIdx.x;
    const int t = threadIdx.x;          // 0..63, owns 8 columns
    const uint4* hb = (const uint4*)g_h;

    const float di = g_dinv[i];
    float acc[8];
    {
        const float4* bp = (const float4*)(bias + t * 8);
        float4 b0 = bp[0], b1 = bp[1];
        acc[0] = b0.x; acc[1] = b0.y; acc[2] = b0.z; acc[3] = b0.w;
        acc[4] = b1.x; acc[5] = b1.y; acc[6] = b1.z; acc[7] = b1.w;
    }
    // self loop: norm = di * 1.0 * di
    fma_h8(acc, hb[(size_t)i * DV8 + t], di * di);

    const int cnt0 = g_cnt[i];
    const int cnt = (cnt0 < CAP) ? cnt0 : CAP;
    const int base = i * CAP;
    int k = 0;
    for (; k + 3 < cnt; k += 4) {
        int r0 = g_esrc[base + k],     r1 = g_esrc[base + k + 1];
        int r2 = g_esrc[base + k + 2], r3 = g_esrc[base + k + 3];
        float n0 = g_dinv[r0] * g_ew[base + k]     * di;
        float n1 = g_dinv[r1] * g_ew[base + k + 1] * di;
        float n2 = g_dinv[r2] * g_ew[base + k + 2] * di;
        float n3 = g_dinv[r3] * g_ew[base + k + 3] * di;
        uint4 v0 = hb[(size_t)r0 * DV8 + t];
        uint4 v1 = hb[(size_t)r1 * DV8 + t];
        uint4 v2 = hb[(size_t)r2 * DV8 + t];
        uint4 v3 = hb[(size_t)r3 * DV8 + t];
        fma_h8(acc, v0, n0);
        fma_h8(acc, v1, n1);
        fma_h8(acc, v2, n2);
        fma_h8(acc, v3, n3);
    }
    for (; k < cnt; ++k) {
        int r0 = g_esrc[base + k];
        float n0 = g_dinv[r0] * g_ew[base + k] * di;
        fma_h8(acc, hb[(size_t)r0 * DV8 + t], n0);
    }

    float4* op = (float4*)(out + (size_t)i * DD + t * 8);
    op[0] = make_float4(acc[0], acc[1], acc[2], acc[3]);
    op[1] = make_float4(acc[4], acc[5], acc[6], acc[7]);
}

// =================== launcher ===================
extern "C" void kernel_launch(void* const* d_in, const int* in_sizes, int n_in,
                              void* d_out, int out_size) {
    const float* x    = (const float*)d_in[0];       // [NN, DD]
    const int*   eidx = (const int*)d_in[1];         // [2, EE] int32
    const float* ea   = (const float*)d_in[2];       // [EE]
    const float* W    = (const float*)d_in[3];       // [DD, DD]
    const float* b    = (const float*)d_in[4];       // [DD]
    float*       out  = (float*)d_out;               // [NN, DD]

    static cudaStream_t s2 = nullptr;
    static cudaEvent_t evFork = nullptr, evJoin = nullptr;
    static void *p_deg = nullptr, *p_cnt = nullptr;
    if (s2 == nullptr) {
        cudaStreamCreateWithFlags(&s2, cudaStreamNonBlocking);
        cudaEventCreateWithFlags(&evFork, cudaEventDisableTiming);
        cudaEventCreateWithFlags(&evJoin, cudaEventDisableTiming);
        cudaGetSymbolAddress(&p_deg, g_deg);
        cudaGetSymbolAddress(&p_cnt, g_cnt);
        cudaFuncSetAttribute(gemm_kernel,
                             cudaFuncAttributeMaxDynamicSharedMemorySize, GEMM_SMEM);
    }

    // fork bucket-build chain onto s2
    cudaEventRecord(evFork, 0);
    cudaStreamWaitEvent(s2, evFork, 0);
    cudaMemsetAsync(p_deg, 0, NN * sizeof(float), s2);
    cudaMemsetAsync(p_cnt, 0, NN * sizeof(int), s2);
    degfill_kernel<<<(EE + 255) / 256, 256, 0, s2>>>(eidx, ea);
    dinv_kernel<<<(NN + 255) / 256, 256, 0, s2>>>();
    cudaEventRecord(evJoin, s2);

    // main stream: prep then GEMM
    prep_kernel<<<3012, 256>>>(x, W);
    dim3 ggrid(DD / 128, (NN + MT - 1) / MT);        // (4, 63) = 252 CTAs
    gemm_kernel<<<ggrid, 256, GEMM_SMEM>>>();

    // join, then aggregate
    cudaStreamWaitEvent(0, evJoin, 0);
    agg_kernel<<<NN, 64>>>(b, out);
}

// round 16
// speedup vs baseline: 1.1156x; 1.0099x over previous
#include <cuda_runtime.h>
#include <cuda_bf16.h>
#include <cuda_fp16.h>
#include <stdint.h>

// Problem constants
#define NN 10000          // nodes
#define EE 160000         // edges
#define DD 512            // feature dim (in == out)
#define DV8 (DD/8)        // 64 uint4-of-half per row
#define CAP 64            // per-node edge bucket capacity (P(deg>=64) ~ 1e-20)

// ---------------- device scratch (no allocs allowed) ----------------
__device__ float g_deg[NN];                       // weighted in-degree sums
__device__ int   g_cnt[NN];                       // per-node bucket fill count
__device__ float g_dinv[NN];                      // rsqrt(1 + deg)
__device__ int   g_esrc[(size_t)NN * CAP];        // bucket: source node
__device__ float g_ew[(size_t)NN * CAP];          // bucket: edge weight
__device__ __half g_h[(size_t)NN * DD];           // h = x @ W (fp16, 10.2 MB)
__device__ __half g_x16[(size_t)NN * DD];         // x in fp16 (10.2 MB)
__device__ __half g_wt[(size_t)DD * DD];          // W^T: [n][k] fp16

// =================== helpers ===================
__device__ __forceinline__ uint32_t smem_to_u32(const void* p) {
    uint32_t a;
    asm("{ .reg .u64 t; cvta.to.shared.u64 t, %1; cvt.u32.u64 %0, t; }"
        : "=r"(a) : "l"(p));
    return a;
}
// XOR swizzle for 64B rows
#define SWZ64(o) ((o) ^ (((o) >> 3) & 0x30))

__device__ __forceinline__ void ldsm_x4(uint32_t r[4], uint32_t addr) {
    asm volatile("ldmatrix.sync.aligned.m8n8.x4.shared.b16 {%0,%1,%2,%3}, [%4];"
                 : "=r"(r[0]), "=r"(r[1]), "=r"(r[2]), "=r"(r[3]) : "r"(addr));
}
__device__ __forceinline__ void mma16816(float c[4], const uint32_t a[4],
                                         uint32_t b0, uint32_t b1) {
    asm volatile(
        "mma.sync.aligned.m16n8k16.row.col.f32.f16.f16.f32 "
        "{%0,%1,%2,%3}, {%4,%5,%6,%7}, {%8,%9}, {%0,%1,%2,%3};"
        : "+f"(c[0]), "+f"(c[1]), "+f"(c[2]), "+f"(c[3])
        : "r"(a[0]), "r"(a[1]), "r"(a[2]), "r"(a[3]), "r"(b0), "r"(b1));
}
__device__ __forceinline__ void cp16(uint32_t dst, const void* src) {
    asm volatile("cp.async.cg.shared.global [%0], [%1], 16;"
                 :: "r"(dst), "l"(src));
}
#define CP_COMMIT() asm volatile("cp.async.commit_group;" ::: "memory")
#define CP_WAIT1()  asm volatile("cp.async.wait_group 1;" ::: "memory")
#define CP_WAIT0()  asm volatile("cp.async.wait_group 0;" ::: "memory")

// =================== prep: x -> fp16; W -> transposed fp16 ===================
// blocks [0,2500): x convert; [2500,3012): W cols
__global__ void prep_kernel(const float* __restrict__ x,
                            const float* __restrict__ W) {
    const int bid = blockIdx.x;
    if (bid < 2500) {
        size_t i = (size_t)bid * 512 + threadIdx.x * 2;   // float4 index (2/thread)
        const float4* xp = (const float4*)x;
#pragma unroll
        for (int q = 0; q < 2; ++q) {
            float4 v = xp[i + q];
            __half2 p0 = __floats2half2_rn(v.x, v.y);
            __half2 p1 = __floats2half2_rn(v.z, v.w);
            uint2 pk;
            pk.x = *(uint32_t*)&p0; pk.y = *(uint32_t*)&p1;
            ((uint2*)g_x16)[i + q] = pk;
        }
    } else {
        int n = bid - 2500;
        for (int k = threadIdx.x; k < DD; k += 256) {
            float v = W[(size_t)k * DD + n];
            g_wt[(size_t)n * DD + k] = __float2half_rn(v);
        }
    }
}

// =================== bucket build (stream 2) ===================
__global__ void degfill_kernel(const int* __restrict__ eidx,
                               const float* __restrict__ ew) {
    int e = blockIdx.x * blockDim.x + threadIdx.x;
    if (e < EE) {
        int r = eidx[e];
        int c = eidx[EE + e];
        float w = ew[e];
        atomicAdd(&g_deg[c], w);
        int p = atomicAdd(&g_cnt[c], 1);
        if (p < CAP) {
            g_esrc[(size_t)c * CAP + p] = r;
            g_ew[(size_t)c * CAP + p]   = w;
        }
    }
}

__global__ void dinv_kernel() {
    int i = blockIdx.x * blockDim.x + threadIdx.x;
    if (i < NN) g_dinv[i] = rsqrtf(1.0f + g_deg[i]);   // self-loop weight 1.0
}

// =================== mma.sync fp16 GEMM: g_h = x16 @ W16 ===================
// CTA tile 128(M) x 128(N), 256 threads (2x4 warps, warp tile 64x32) — R10/R11 shape.
// K-chunk 32, 3-stage cp.async, SINGLE sync per chunk (prefetch after compute).
// Stage (16KB): A 0..8K | B 8K..16K ; 64B rows, SW64.
#define KC 32
#define NCH (DD / KC)            // 16
#define STAGE 16384
#define NSTG 3
#define GEMM_SMEM (NSTG * STAGE) // 49152

__device__ __forceinline__ void gemm_load_stage(uint32_t sb, int stOff, int kc,
                                                int tid, int mBase, int nBase) {
    const int kOff = kc * KC;
#pragma unroll
    for (int it = 0; it < 4; ++it) {
        int vv = tid + it * 256;            // 0..1023
        int row = (vv & 511) >> 2;          // 0..127
        int g   = vv & 3;                   // 16B unit
        const __half* srcp;
        int region;
        size_t srcRow;
        if (vv < 512) {
            int m = mBase + row; if (m > NN - 1) m = NN - 1;
            srcp = g_x16;
            region = 0;
            srcRow = (size_t)m;
        } else {
            srcp = g_wt;
            region = 8192;
            srcRow = (size_t)(nBase + row);
        }
        cp16(sb + stOff + region + SWZ64(row * 64 + g * 16),
             srcp + srcRow * DD + kOff + g * 8);
    }
}

__global__ void __launch_bounds__(256, 2)
gemm_kernel() {
    extern __shared__ char smem[];
    const uint32_t sb = smem_to_u32(smem);
    const int tid  = threadIdx.x;
    const int wid  = tid >> 5;
    const int lane = tid & 31;
    const int wy   = wid >> 2;            // 0..1  (M)
    const int wx   = wid & 3;             // 0..3  (N)
    const int mBase = blockIdx.y * 128;
    const int nBase = blockIdx.x * 128;

    float c[4][4][4];                      // warp tile 64x32
#pragma unroll
    for (int i = 0; i < 4; ++i)
#pragma unroll
        for (int j = 0; j < 4; ++j)
#pragma unroll
            for (int r = 0; r < 4; ++r) c[i][j][r] = 0.0f;

    const int aRow = wy * 64 + (lane & 15);
    const int aKu  = (lane >> 4);
    const int bRow = wx * 32 + (lane & 7) + ((lane >> 4) & 1) * 8;
    const int bKu  = ((lane >> 3) & 1);

    gemm_load_stage(sb, 0, 0, tid, mBase, nBase);
    CP_COMMIT();
    gemm_load_stage(sb, STAGE, 1, tid, mBase, nBase);
    CP_COMMIT();

    for (int kc = 0; kc < NCH; ++kc) {
        const int stOff = (kc % NSTG) * STAGE;
        // stage kc ready when at most 1 newer group still in flight
        if (kc + 1 < NCH) { CP_WAIT1(); } else { CP_WAIT0(); }
        __syncthreads();                   // single barrier per chunk

#pragma unroll
        for (int k16 = 0; k16 < 2; ++k16) {
            const int kb = k16 * 2;
            uint32_t a[4][4], b[2][4];
#pragma unroll
            for (int mt = 0; mt < 4; ++mt) {
                int off = SWZ64((aRow + mt * 16) * 64 + (kb + aKu) * 16);
                ldsm_x4(a[mt], sb + stOff + 0 + off);
            }
#pragma unroll
            for (int pr = 0; pr < 2; ++pr) {
                int off = SWZ64((bRow + pr * 16) * 64 + (kb + bKu) * 16);
                ldsm_x4(b[pr], sb + stOff + 8192 + off);
            }
#pragma unroll
            for (int mt = 0; mt < 4; ++mt)
#pragma unroll
                for (int nt = 0; nt < 4; ++nt)
                    mma16816(c[mt][nt], a[mt], b[nt >> 1][(nt & 1) * 2],
                             b[nt >> 1][(nt & 1) * 2 + 1]);
        }

        // prefetch chunk kc+2 into stage (kc+2)%3 == (kc-1)%3.
        // Safe: the barrier above guarantees every warp finished reading
        // stage (kc-1)%3 (compute of iter kc-1); laggards read kc%3 only.
        if (kc + 2 < NCH) {
            gemm_load_stage(sb, ((kc + 2) % NSTG) * STAGE, kc + 2, tid, mBase, nBase);
            CP_COMMIT();
        }
    }

    // epilogue: half2 stores to g_h
    const int erow = mBase + wy * 64 + (lane >> 2);
    const int ecol = nBase + wx * 32 + (lane & 3) * 2;
#pragma unroll
    for (int mt = 0; mt < 4; ++mt) {
#pragma unroll
        for (int nt = 0; nt < 4; ++nt) {
            int r0 = erow + mt * 16;
            int cc = ecol + nt * 8;
            if (r0 < NN) {
                __half2 p = __floats2half2_rn(c[mt][nt][0], c[mt][nt][1]);
                *(__half2*)&g_h[(size_t)r0 * DD + cc] = p;
            }
            if (r0 + 8 < NN) {
                __half2 p = __floats2half2_rn(c[mt][nt][2], c[mt][nt][3]);
                *(__half2*)&g_h[(size_t)(r0 + 8) * DD + cc] = p;
            }
        }
    }
}

// =================== aggregation (fp16 rows, 64 threads/node, unroll 4) ===================
__device__ __forceinline__ void fma_h8(float acc[8], uint4 v, float n) {
    __half2* hp = (__half2*)&v;
#pragma unroll
    for (int q = 0; q < 4; ++q) {
        float2 f = __half22float2(hp[q]);
        acc[q * 2 + 0] += f.x * n;
        acc[q * 2 + 1] += f.y * n;
    }
}

__global__ __launch_bounds__(64)
void agg_kernel(const float* __restrict__ bias,
                float* __restrict__ out) {
    const int i = blockIdx.x;
    const int t = threadIdx.x;          // 0..63, owns 8 columns
    const uint4* hb = (const uint4*)g_h;

    const float di = g_dinv[i];
    float acc[8];
    {
        const float4* bp = (const float4*)(bias + t * 8);
        float4 b0 = bp[0], b1 = bp[1];
        acc[0] = b0.x; acc[1] = b0.y; acc[2] = b0.z; acc[3] = b0.w;
        acc[4] = b1.x; acc[5] = b1.y; acc[6] = b1.z; acc[7] = b1.w;
    }
    // self loop: norm = di * 1.0 * di
    fma_h8(acc, hb[(size_t)i * DV8 + t], di * di);

    const int cnt0 = g_cnt[i];
    const int cnt = (cnt0 < CAP) ? cnt0 : CAP;
    const int base = i * CAP;
    int k = 0;
    for (; k + 3 < cnt; k += 4) {
        int r0 = g_esrc[base + k],     r1 = g_esrc[base + k + 1];
        int r2 = g_esrc[base + k + 2], r3 = g_esrc[base + k + 3];
        float n0 = g_dinv[r0] * g_ew[base + k]     * di;
        float n1 = g_dinv[r1] * g_ew[base + k + 1] * di;
        float n2 = g_dinv[r2] * g_ew[base + k + 2] * di;
        float n3 = g_dinv[r3] * g_ew[base + k + 3] * di;
        uint4 v0 = hb[(size_t)r0 * DV8 + t];
        uint4 v1 = hb[(size_t)r1 * DV8 + t];
        uint4 v2 = hb[(size_t)r2 * DV8 + t];
        uint4 v3 = hb[(size_t)r3 * DV8 + t];
        fma_h8(acc, v0, n0);
        fma_h8(acc, v1, n1);
        fma_h8(acc, v2, n2);
        fma_h8(acc, v3, n3);
    }
    for (; k < cnt; ++k) {
        int r0 = g_esrc[base + k];
        float n0 = g_dinv[r0] * g_ew[base + k] * di;
        fma_h8(acc, hb[(size_t)r0 * DV8 + t], n0);
    }

    float4* op = (float4*)(out + (size_t)i * DD + t * 8);
    op[0] = make_float4(acc[0], acc[1], acc[2], acc[3]);
    op[1] = make_float4(acc[4], acc[5], acc[6], acc[7]);
}

// =================== launcher ===================
extern "C" void kernel_launch(void* const* d_in, const int* in_sizes, int n_in,
                              void* d_out, int out_size) {
    const float* x    = (const float*)d_in[0];       // [NN, DD]
    const int*   eidx = (const int*)d_in[1];         // [2, EE] int32
    const float* ea   = (const float*)d_in[2];       // [EE]
    const float* W    = (const float*)d_in[3];       // [DD, DD]
    const float* b    = (const float*)d_in[4];       // [DD]
    float*       out  = (float*)d_out;               // [NN, DD]

    static cudaStream_t s2 = nullptr;
    static cudaEvent_t evFork = nullptr, evJoin = nullptr;
    static void *p_deg = nullptr, *p_cnt = nullptr;
    if (s2 == nullptr) {
        cudaStreamCreateWithFlags(&s2, cudaStreamNonBlocking);
        cudaEventCreateWithFlags(&evFork, cudaEventDisableTiming);
        cudaEventCreateWithFlags(&evJoin, cudaEventDisableTiming);
        cudaGetSymbolAddress(&p_deg, g_deg);
        cudaGetSymbolAddress(&p_cnt, g_cnt);
        cudaFuncSetAttribute(gemm_kernel,
                             cudaFuncAttributeMaxDynamicSharedMemorySize, GEMM_SMEM);
    }

    // fork bucket-build chain onto s2
    cudaEventRecord(evFork, 0);
    cudaStreamWaitEvent(s2, evFork, 0);
    cudaMemsetAsync(p_deg, 0, NN * sizeof(float), s2);
    cudaMemsetAsync(p_cnt, 0, NN * sizeof(int), s2);
    degfill_kernel<<<(EE + 255) / 256, 256, 0, s2>>>(eidx, ea);
    dinv_kernel<<<(NN + 255) / 256, 256, 0, s2>>>();
    cudaEventRecord(evJoin, s2);

    // main stream: prep then GEMM
    prep_kernel<<<3012, 256>>>(x, W);
    dim3 ggrid(DD / 128, (NN + 127) / 128);          // (4, 79) = 316 CTAs
    gemm_kernel<<<ggrid, 256, GEMM_SMEM>>>();

    // join, then aggregate
    cudaStreamWaitEvent(0, evJoin, 0);
    agg_kernel<<<NN, 64>>>(b, out);
}

// round 17
// speedup vs baseline: 1.1736x; 1.0520x over previous
#include <cuda_runtime.h>
#include <cuda_bf16.h>
#include <cuda_fp16.h>
#include <stdint.h>

// Problem constants
#define NN 10000          // nodes
#define EE 160000         // edges
#define DD 512            // feature dim (in == out)
#define DV8 (DD/8)        // 64 uint4-of-half per row
#define CAP 64            // per-node edge bucket capacity (P(deg>=64) ~ 1e-20)

// ---------------- device scratch (no allocs allowed) ----------------
__device__ int2  g_dc[NN];                        // .x = cnt, .y = deg (float bits); one memset
__device__ int   g_esrc[(size_t)NN * CAP];        // bucket: source node
__device__ float g_ew[(size_t)NN * CAP];          // bucket: edge weight
__device__ __half g_h[(size_t)NN * DD];           // h = x @ W (fp16, 10.2 MB)
__device__ __half g_x16[(size_t)NN * DD];         // x in fp16 (10.2 MB)
__device__ __half g_wt[(size_t)DD * DD];          // W^T: [n][k] fp16

// =================== helpers ===================
__device__ __forceinline__ uint32_t smem_to_u32(const void* p) {
    uint32_t a;
    asm("{ .reg .u64 t; cvta.to.shared.u64 t, %1; cvt.u32.u64 %0, t; }"
        : "=r"(a) : "l"(p));
    return a;
}
// XOR swizzle for 64B rows
#define SWZ64(o) ((o) ^ (((o) >> 3) & 0x30))

__device__ __forceinline__ void ldsm_x4(uint32_t r[4], uint32_t addr) {
    asm volatile("ldmatrix.sync.aligned.m8n8.x4.shared.b16 {%0,%1,%2,%3}, [%4];"
                 : "=r"(r[0]), "=r"(r[1]), "=r"(r[2]), "=r"(r[3]) : "r"(addr));
}
__device__ __forceinline__ void mma16816(float c[4], const uint32_t a[4],
                                         uint32_t b0, uint32_t b1) {
    asm volatile(
        "mma.sync.aligned.m16n8k16.row.col.f32.f16.f16.f32 "
        "{%0,%1,%2,%3}, {%4,%5,%6,%7}, {%8,%9}, {%0,%1,%2,%3};"
        : "+f"(c[0]), "+f"(c[1]), "+f"(c[2]), "+f"(c[3])
        : "r"(a[0]), "r"(a[1]), "r"(a[2]), "r"(a[3]), "r"(b0), "r"(b1));
}
__device__ __forceinline__ void cp16(uint32_t dst, const void* src) {
    asm volatile("cp.async.cg.shared.global [%0], [%1], 16;"
                 :: "r"(dst), "l"(src));
}
#define CP_COMMIT() asm volatile("cp.async.commit_group;" ::: "memory")
#define CP_WAIT1()  asm volatile("cp.async.wait_group 1;" ::: "memory")
#define CP_WAIT0()  asm volatile("cp.async.wait_group 0;" ::: "memory")

// =================== prep: x -> fp16; W -> transposed fp16 ===================
// blocks [0,2500): x convert; [2500,3012): W cols
__global__ void prep_kernel(const float* __restrict__ x,
                            const float* __restrict__ W) {
    const int bid = blockIdx.x;
    if (bid < 2500) {
        size_t i = (size_t)bid * 512 + threadIdx.x * 2;   // float4 index (2/thread)
        const float4* xp = (const float4*)x;
#pragma unroll
        for (int q = 0; q < 2; ++q) {
            float4 v = xp[i + q];
            __half2 p0 = __floats2half2_rn(v.x, v.y);
            __half2 p1 = __floats2half2_rn(v.z, v.w);
            uint2 pk;
            pk.x = *(uint32_t*)&p0; pk.y = *(uint32_t*)&p1;
            ((uint2*)g_x16)[i + q] = pk;
        }
    } else {
        int n = bid - 2500;
        for (int k = threadIdx.x; k < DD; k += 256) {
            float v = W[(size_t)k * DD + n];
            g_wt[(size_t)n * DD + k] = __float2half_rn(v);
        }
    }
}

// =================== bucket build (stream 2) ===================
__global__ void degfill_kernel(const int* __restrict__ eidx,
                               const float* __restrict__ ew) {
    int e = blockIdx.x * blockDim.x + threadIdx.x;
    if (e < EE) {
        int r = eidx[e];
        int c = eidx[EE + e];
        float w = ew[e];
        atomicAdd((float*)g_dc + 2 * c + 1, w);          // deg sum
        int p = atomicAdd((int*)g_dc + 2 * c, 1);        // bucket cursor
        if (p < CAP) {
            g_esrc[(size_t)c * CAP + p] = r;
            g_ew[(size_t)c * CAP + p]   = w;
        }
    }
}

// =================== mma.sync fp16 GEMM: g_h = x16 @ W16 ===================
// CTA tile 128(M) x 128(N), 256 threads (2x4 warps, warp tile 64x32).
// K-chunk 32, 3-stage cp.async, single sync per chunk.
// Stage (16KB): A 0..8K | B 8K..16K ; 64B rows, SW64.
#define KC 32
#define NCH (DD / KC)            // 16
#define STAGE 16384
#define NSTG 3
#define GEMM_SMEM (NSTG * STAGE) // 49152

__device__ __forceinline__ void gemm_load_stage(uint32_t sb, int stOff, int kc,
                                                int tid, int mBase, int nBase) {
    const int kOff = kc * KC;
#pragma unroll
    for (int it = 0; it < 4; ++it) {
        int vv = tid + it * 256;            // 0..1023
        int row = (vv & 511) >> 2;          // 0..127
        int g   = vv & 3;                   // 16B unit
        const __half* srcp;
        int region;
        size_t srcRow;
        if (vv < 512) {
            int m = mBase + row; if (m > NN - 1) m = NN - 1;
            srcp = g_x16;
            region = 0;
            srcRow = (size_t)m;
        } else {
            srcp = g_wt;
            region = 8192;
            srcRow = (size_t)(nBase + row);
        }
        cp16(sb + stOff + region + SWZ64(row * 64 + g * 16),
             srcp + srcRow * DD + kOff + g * 8);
    }
}

__global__ void __launch_bounds__(256, 2)
gemm_kernel() {
    extern __shared__ char smem[];
    const uint32_t sb = smem_to_u32(smem);
    const int tid  = threadIdx.x;
    const int wid  = tid >> 5;
    const int lane = tid & 31;
    const int wy   = wid >> 2;            // 0..1  (M)
    const int wx   = wid & 3;             // 0..3  (N)
    const int mBase = blockIdx.y * 128;
    const int nBase = blockIdx.x * 128;

    float c[4][4][4];                      // warp tile 64x32
#pragma unroll
    for (int i = 0; i < 4; ++i)
#pragma unroll
        for (int j = 0; j < 4; ++j)
#pragma unroll
            for (int r = 0; r < 4; ++r) c[i][j][r] = 0.0f;

    const int aRow = wy * 64 + (lane & 15);
    const int aKu  = (lane >> 4);
    const int bRow = wx * 32 + (lane & 7) + ((lane >> 4) & 1) * 8;
    const int bKu  = ((lane >> 3) & 1);

    gemm_load_stage(sb, 0, 0, tid, mBase, nBase);
    CP_COMMIT();
    gemm_load_stage(sb, STAGE, 1, tid, mBase, nBase);
    CP_COMMIT();

    for (int kc = 0; kc < NCH; ++kc) {
        const int stOff = (kc % NSTG) * STAGE;
        if (kc + 1 < NCH) { CP_WAIT1(); } else { CP_WAIT0(); }
        __syncthreads();                   // single barrier per chunk

#pragma unroll
        for (int k16 = 0; k16 < 2; ++k16) {
            const int kb = k16 * 2;
            uint32_t a[4][4], b[2][4];
#pragma unroll
            for (int mt = 0; mt < 4; ++mt) {
                int off = SWZ64((aRow + mt * 16) * 64 + (kb + aKu) * 16);
                ldsm_x4(a[mt], sb + stOff + 0 + off);
            }
#pragma unroll
            for (int pr = 0; pr < 2; ++pr) {
                int off = SWZ64((bRow + pr * 16) * 64 + (kb + bKu) * 16);
                ldsm_x4(b[pr], sb + stOff + 8192 + off);
            }
#pragma unroll
            for (int mt = 0; mt < 4; ++mt)
#pragma unroll
                for (int nt = 0; nt < 4; ++nt)
                    mma16816(c[mt][nt], a[mt], b[nt >> 1][(nt & 1) * 2],
                             b[nt >> 1][(nt & 1) * 2 + 1]);
        }

        // prefetch chunk kc+2 into stage (kc-1)%3 (safe: barrier above fenced its readers)
        if (kc + 2 < NCH) {
            gemm_load_stage(sb, ((kc + 2) % NSTG) * STAGE, kc + 2, tid, mBase, nBase);
            CP_COMMIT();
        }
    }

    // epilogue: half2 stores to g_h
    const int erow = mBase + wy * 64 + (lane >> 2);
    const int ecol = nBase + wx * 32 + (lane & 3) * 2;
#pragma unroll
    for (int mt = 0; mt < 4; ++mt) {
#pragma unroll
        for (int nt = 0; nt < 4; ++nt) {
            int r0 = erow + mt * 16;
            int cc = ecol + nt * 8;
            if (r0 < NN) {
                __half2 p = __floats2half2_rn(c[mt][nt][0], c[mt][nt][1]);
                *(__half2*)&g_h[(size_t)r0 * DD + cc] = p;
            }
            if (r0 + 8 < NN) {
                __half2 p = __floats2half2_rn(c[mt][nt][2], c[mt][nt][3]);
                *(__half2*)&g_h[(size_t)(r0 + 8) * DD + cc] = p;
            }
        }
    }
}

// =================== aggregation (fp16 rows; norms precomputed in smem) ===================
__device__ __forceinline__ void fma_h8(float acc[8], uint4 v, float n) {
    __half2* hp = (__half2*)&v;
#pragma unroll
    for (int q = 0; q < 4; ++q) {
        float2 f = __half22float2(hp[q]);
        acc[q * 2 + 0] += f.x * n;
        acc[q * 2 + 1] += f.y * n;
    }
}

__global__ __launch_bounds__(64)
void agg_kernel(const float* __restrict__ bias,
                float* __restrict__ out) {
    __shared__ float snorm[CAP];
    __shared__ int   ssrc[CAP];
    const int i = blockIdx.x;
    const int t = threadIdx.x;          // 0..63, owns 8 columns; also 1 edge in prologue
    const uint4* hb = (const uint4*)g_h;

    const int2 dc = g_dc[i];
    const float di = rsqrtf(1.0f + __int_as_float(dc.y));   // self-loop weight 1.0
    const int cnt = (dc.x < CAP) ? dc.x : CAP;

    // each thread resolves one edge's (src, norm) into smem (<= CAP = 64 = blockDim)
    if (t < cnt) {
        int r = g_esrc[(size_t)i * CAP + t];
        float w = g_ew[(size_t)i * CAP + t];
        float dr = rsqrtf(1.0f + __int_as_float(g_dc[r].y));
        ssrc[t]  = r;
        snorm[t] = dr * w * di;
    }
    __syncthreads();

    float acc[8];
    {
        const float4* bp = (const float4*)(bias + t * 8);
        float4 b0 = bp[0], b1 = bp[1];
        acc[0] = b0.x; acc[1] = b0.y; acc[2] = b0.z; acc[3] = b0.w;
        acc[4] = b1.x; acc[5] = b1.y; acc[6] = b1.z; acc[7] = b1.w;
    }
    // self loop: norm = di * 1.0 * di
    fma_h8(acc, hb[(size_t)i * DV8 + t], di * di);

    int k = 0;
    for (; k + 3 < cnt; k += 4) {
        int r0 = ssrc[k],     r1 = ssrc[k + 1];
        int r2 = ssrc[k + 2], r3 = ssrc[k + 3];
        float n0 = snorm[k],     n1 = snorm[k + 1];
        float n2 = snorm[k + 2], n3 = snorm[k + 3];
        uint4 v0 = hb[(size_t)r0 * DV8 + t];
        uint4 v1 = hb[(size_t)r1 * DV8 + t];
        uint4 v2 = hb[(size_t)r2 * DV8 + t];
        uint4 v3 = hb[(size_t)r3 * DV8 + t];
        fma_h8(acc, v0, n0);
        fma_h8(acc, v1, n1);
        fma_h8(acc, v2, n2);
        fma_h8(acc, v3, n3);
    }
    for (; k < cnt; ++k)
        fma_h8(acc, hb[(size_t)ssrc[k] * DV8 + t], snorm[k]);

    float4* op = (float4*)(out + (size_t)i * DD + t * 8);
    op[0] = make_float4(acc[0], acc[1], acc[2], acc[3]);
    op[1] = make_float4(acc[4], acc[5], acc[6], acc[7]);
}

// =================== launcher ===================
extern "C" void kernel_launch(void* const* d_in, const int* in_sizes, int n_in,
                              void* d_out, int out_size) {
    const float* x    = (const float*)d_in[0];       // [NN, DD]
    const int*   eidx = (const int*)d_in[1];         // [2, EE] int32
    const float* ea   = (const float*)d_in[2];       // [EE]
    const float* W    = (const float*)d_in[3];       // [DD, DD]
    const float* b    = (const float*)d_in[4];       // [DD]
    float*       out  = (float*)d_out;               // [NN, DD]

    static cudaStream_t s2 = nullptr;
    static cudaEvent_t evFork = nullptr, evJoin = nullptr;
    static void* p_dc = nullptr;
    if (s2 == nullptr) {
        cudaStreamCreateWithFlags(&s2, cudaStreamNonBlocking);
        cudaEventCreateWithFlags(&evFork, cudaEventDisableTiming);
        cudaEventCreateWithFlags(&evJoin, cudaEventDisableTiming);
        cudaGetSymbolAddress(&p_dc, g_dc);
        cudaFuncSetAttribute(gemm_kernel,
                             cudaFuncAttributeMaxDynamicSharedMemorySize, GEMM_SMEM);
    }

    // fork bucket-build chain onto s2 (memset + degfill only)
    cudaEventRecord(evFork, 0);
    cudaStreamWaitEvent(s2, evFork, 0);
    cudaMemsetAsync(p_dc, 0, NN * sizeof(int2), s2);
    degfill_kernel<<<(EE + 255) / 256, 256, 0, s2>>>(eidx, ea);
    cudaEventRecord(evJoin, s2);

    // main stream: prep then GEMM
    prep_kernel<<<3012, 256>>>(x, W);
    dim3 ggrid(DD / 128, (NN + 127) / 128);          // (4, 79) = 316 CTAs
    gemm_kernel<<<ggrid, 256, GEMM_SMEM>>>();

    // join, then aggregate
    cudaStreamWaitEvent(0, evJoin, 0);
    agg_kernel<<<NN, 64>>>(b, out);
}